// round 1
// baseline (speedup 1.0000x reference)
#include <cuda_runtime.h>
#include <math.h>

#define B_ 2048
#define T_ 200
#define C_ 128
#define THREADS 256
#define PADV (-4294967295.0f)
#define QBT 32   // batches per CTA in query kernel

// scratch for the precomputed query (allocation-free: __device__ global)
__device__ float g_query[(size_t)B_ * C_];

// ---------------------------------------------------------------------------
// Kernel 1: q = tanh(uq @ W + b), W staged in SMEM once per CTA (32 batches)
// ---------------------------------------------------------------------------
__global__ void query_kernel(const float* __restrict__ uq,
                             const float* __restrict__ W,
                             const float* __restrict__ bias) {
    extern __shared__ float qs[];          // sW[C*C] + suq[QBT*C]
    float* sW  = qs;
    float* suq = qs + C_ * C_;

    const int tid = threadIdx.x;
    const int b0  = blockIdx.x * QBT;

    const float4* W4  = (const float4*)W;
    float4*       sW4 = (float4*)sW;
    #pragma unroll
    for (int i = tid; i < C_ * C_ / 4; i += THREADS) sW4[i] = W4[i];

    const float4* uq4  = (const float4*)(uq + (size_t)b0 * C_);
    float4*       suq4 = (float4*)suq;
    for (int i = tid; i < QBT * C_ / 4; i += THREADS) suq4[i] = uq4[i];
    __syncthreads();

    const int c   = tid & (C_ - 1);
    const int bl0 = tid >> 7;              // 0..1
    const float bc = bias[c];

    for (int bl = bl0; bl < QBT; bl += THREADS / C_) {
        float acc = bc;
        const float* uqr = suq + bl * C_;
        #pragma unroll 16
        for (int d = 0; d < C_; d++)
            acc = fmaf(uqr[d], sW[d * C_ + c], acc);
        g_query[(size_t)(b0 + bl) * C_ + c] = tanhf(acc);
    }
}

// ---------------------------------------------------------------------------
// Kernel 2: per-batch attention, keys slice staged once in SMEM via cp.async
// ---------------------------------------------------------------------------
// SMEM floats: keys 25600 | q 128 | align 256 | acc partials 1024 | scratch 32
#define SM_KEYS   0
#define SM_Q      (T_ * C_)
#define SM_ALIGN  (SM_Q + C_)
#define SM_ACC    (SM_ALIGN + 256)
#define SM_SCR    (SM_ACC + 8 * 32 * 4)
#define SM_FLOATS (SM_SCR + 32)
#define SMEM_BYTES (SM_FLOATS * 4)

__global__ void attn_kernel(const float* __restrict__ keys,
                            const int*   __restrict__ keys_length,
                            float*       __restrict__ out) {
    extern __shared__ float smem[];
    float4* sk4    = (float4*)(smem + SM_KEYS);     // [T_*32] float4
    float*  sq     = smem + SM_Q;
    float*  salign = smem + SM_ALIGN;
    float4* sacc   = (float4*)(smem + SM_ACC);      // [8*32] float4
    float*  sscr   = smem + SM_SCR;

    const int tid  = threadIdx.x;
    const int b    = blockIdx.x;
    const int lane = tid & 31;
    const int w    = tid >> 5;                      // 0..7

    // --- stage keys[b] (100 KB) into SMEM with cp.async ---
    const float4* gk = (const float4*)(keys + (size_t)b * T_ * C_);
    #pragma unroll 5
    for (int i = tid; i < T_ * C_ / 4; i += THREADS) {
        unsigned int s = (unsigned int)__cvta_generic_to_shared(&sk4[i]);
        asm volatile("cp.async.cg.shared.global [%0], [%1], 16;\n"
                     :: "r"(s), "l"(gk + i));
    }
    asm volatile("cp.async.commit_group;\n" ::: "memory");

    // query + length fetched while keys in flight
    if (tid < C_ / 4)
        ((float4*)sq)[tid] = ((const float4*)(g_query + (size_t)b * C_))[tid];
    const int len = keys_length[b];

    asm volatile("cp.async.wait_group 0;\n" ::: "memory");
    __syncthreads();

    // --- dot products: warp w handles t = w, w+8, ... ---
    const float4 q4 = ((const float4*)sq)[lane];
    const float scale = 0.08838834764831845f;       // 1/sqrt(128)
    for (int t = w; t < T_; t += 8) {
        float4 k4 = sk4[t * 32 + lane];
        float d = q4.x * k4.x + q4.y * k4.y + q4.z * k4.z + q4.w * k4.w;
        #pragma unroll
        for (int off = 16; off; off >>= 1)
            d += __shfl_xor_sync(0xffffffffu, d, off);
        if (lane == 0)
            salign[t] = (t < len) ? d * scale : PADV;
    }
    __syncthreads();

    // --- softmax over salign[0..T) ---
    const float v = (tid < T_) ? salign[tid] : -INFINITY;

    float m = v;
    #pragma unroll
    for (int off = 16; off; off >>= 1)
        m = fmaxf(m, __shfl_xor_sync(0xffffffffu, m, off));
    if (lane == 0) sscr[w] = m;
    __syncthreads();
    if (w == 0) {
        float mm = (lane < 8) ? sscr[lane] : -INFINITY;
        #pragma unroll
        for (int off = 16; off; off >>= 1)
            mm = fmaxf(mm, __shfl_xor_sync(0xffffffffu, mm, off));
        if (lane == 0) sscr[8] = mm;
    }
    __syncthreads();
    const float gmax = sscr[8];

    const float e = (tid < T_) ? expf(v - gmax) : 0.0f;
    float s = e;
    #pragma unroll
    for (int off = 16; off; off >>= 1)
        s += __shfl_xor_sync(0xffffffffu, s, off);
    if (lane == 0) sscr[16 + w] = s;
    __syncthreads();
    if (w == 0) {
        float ss = (lane < 8) ? sscr[16 + lane] : 0.0f;
        #pragma unroll
        for (int off = 16; off; off >>= 1)
            ss += __shfl_xor_sync(0xffffffffu, ss, off);
        if (lane == 0) sscr[9] = ss;
    }
    __syncthreads();
    const float inv = 1.0f / sscr[9];
    // fold the residual mean-pool in: out = sum_t (p[t] + 1/T) * keys[t]
    if (tid < T_) salign[tid] = e * inv + (1.0f / (float)T_);
    __syncthreads();

    // --- weighted sum: warp w handles t in [w*25, (w+1)*25), lane = c-group ---
    float4 acc = make_float4(0.f, 0.f, 0.f, 0.f);
    #pragma unroll
    for (int i = 0; i < 25; i++) {
        int t = w * 25 + i;
        float p = salign[t];
        float4 k4 = sk4[t * 32 + lane];
        acc.x = fmaf(p, k4.x, acc.x);
        acc.y = fmaf(p, k4.y, acc.y);
        acc.z = fmaf(p, k4.z, acc.z);
        acc.w = fmaf(p, k4.w, acc.w);
    }
    sacc[w * 32 + lane] = acc;
    __syncthreads();

    if (tid < 32) {
        float4 r = sacc[tid];
        #pragma unroll
        for (int th = 1; th < 8; th++) {
            float4 a = sacc[th * 32 + tid];
            r.x += a.x; r.y += a.y; r.z += a.z; r.w += a.w;
        }
        ((float4*)(out + (size_t)b * C_))[tid] = r;
    }
}

// ---------------------------------------------------------------------------
extern "C" void kernel_launch(void* const* d_in, const int* in_sizes, int n_in,
                              void* d_out, int out_size) {
    const float* uq   = (const float*)d_in[0];   // [B,1,C]
    const float* keys = (const float*)d_in[1];   // [B,T,C]
    const int*   klen = (const int*)d_in[2];     // [B,1]
    const float* W    = (const float*)d_in[3];   // [C,C]
    const float* bias = (const float*)d_in[4];   // [C]
    float* out = (float*)d_out;                  // [B,1,C]

    const int qsmem = (C_ * C_ + QBT * C_) * sizeof(float);   // 80 KB
    cudaFuncSetAttribute(query_kernel,
                         cudaFuncAttributeMaxDynamicSharedMemorySize, qsmem);
    cudaFuncSetAttribute(attn_kernel,
                         cudaFuncAttributeMaxDynamicSharedMemorySize, SMEM_BYTES);

    query_kernel<<<B_ / QBT, THREADS, qsmem>>>(uq, W, bias);
    attn_kernel<<<B_, THREADS, SMEM_BYTES>>>(keys, klen, out);
}

// round 2
// speedup vs baseline: 1.4185x; 1.4185x over previous
#include <cuda_runtime.h>
#include <math.h>

#define B_ 2048
#define T_ 200
#define C_ 128
#define THREADS 256
#define NW 8
#define TPW (T_ / NW)          // 25 timesteps per warp
#define PADV (-4294967295.0f)
#define QBT 8                  // batches per CTA in query kernel

// precomputed query (allocation-free scratch)
__device__ float g_query[(size_t)B_ * C_];

// ---------------------------------------------------------------------------
// Kernel 1: q = tanh(uq @ W + b). 256 CTAs, W staged in SMEM, 4-way ILP.
// ---------------------------------------------------------------------------
__global__ void query_kernel(const float* __restrict__ uq,
                             const float* __restrict__ W,
                             const float* __restrict__ bias) {
    extern __shared__ float qs[];              // sW[C*C] + suq[QBT*C]
    float* sW  = qs;
    float* suq = qs + C_ * C_;

    const int tid = threadIdx.x;
    const int b0  = blockIdx.x * QBT;

    const float4* W4  = (const float4*)W;
    float4*       sW4 = (float4*)sW;
    #pragma unroll
    for (int i = tid; i < C_ * C_ / 4; i += THREADS) sW4[i] = W4[i];
    ((float4*)suq)[tid] = ((const float4*)(uq + (size_t)b0 * C_))[tid];
    __syncthreads();

    const int c = tid & (C_ - 1);
    const int h = tid >> 7;                    // 0..1
    const float bc = bias[c];

    for (int bl = h; bl < QBT; bl += 2) {
        const float* u = suq + bl * C_;
        float a0 = 0.f, a1 = 0.f, a2 = 0.f, a3 = 0.f;
        #pragma unroll
        for (int d = 0; d < C_; d += 4) {
            a0 = fmaf(u[d + 0], sW[(d + 0) * C_ + c], a0);
            a1 = fmaf(u[d + 1], sW[(d + 1) * C_ + c], a1);
            a2 = fmaf(u[d + 2], sW[(d + 2) * C_ + c], a2);
            a3 = fmaf(u[d + 3], sW[(d + 3) * C_ + c], a3);
        }
        g_query[(size_t)(b0 + bl) * C_ + c] = tanhf((a0 + a1) + (a2 + a3) + bc);
    }
}

// ---------------------------------------------------------------------------
// Kernel 2: single-pass online-softmax attention. keys read from DRAM ONCE,
// each k4 used for dot AND weighted accumulation while in registers.
// ---------------------------------------------------------------------------
__global__ void __launch_bounds__(THREADS)
attn_kernel(const float* __restrict__ keys,
            const int*   __restrict__ keys_length,
            float*       __restrict__ out) {
    __shared__ float  sm_m[NW];
    __shared__ float  sm_s[NW];
    __shared__ float4 sm_acc[NW * 32];
    __shared__ float4 sm_ksum[NW * 32];

    const int tid  = threadIdx.x;
    const int b    = blockIdx.x;
    const int lane = tid & 31;
    const int w    = tid >> 5;

    const float4 q4  = ((const float4*)(g_query + (size_t)b * C_))[lane];
    const int    len = keys_length[b];
    const float4* gk = (const float4*)(keys + (size_t)b * T_ * C_);

    const float scale = 0.08838834764831845f;  // 1/sqrt(128)

    float  m = -INFINITY, s = 0.f;
    float4 acc  = make_float4(0.f, 0.f, 0.f, 0.f);
    float4 ksum = make_float4(0.f, 0.f, 0.f, 0.f);

    #pragma unroll 5
    for (int i = 0; i < TPW; i++) {
        const int t = w + i * NW;
        const float4 k4 = gk[t * 32 + lane];

        ksum.x += k4.x; ksum.y += k4.y; ksum.z += k4.z; ksum.w += k4.w;

        float d = q4.x * k4.x + q4.y * k4.y + q4.z * k4.z + q4.w * k4.w;
        #pragma unroll
        for (int off = 16; off; off >>= 1)
            d += __shfl_xor_sync(0xffffffffu, d, off);

        const float val = (t < len) ? d * scale : PADV;

        if (val > m) {                          // warp-uniform branch
            const float f = __expf(m - val);    // exp(-inf)=0 handles init
            s = fmaf(s, f, 1.0f);
            acc.x = fmaf(acc.x, f, k4.x);
            acc.y = fmaf(acc.y, f, k4.y);
            acc.z = fmaf(acc.z, f, k4.z);
            acc.w = fmaf(acc.w, f, k4.w);
            m = val;
        } else {
            const float e = __expf(val - m);
            s += e;
            acc.x = fmaf(e, k4.x, acc.x);
            acc.y = fmaf(e, k4.y, acc.y);
            acc.z = fmaf(e, k4.z, acc.z);
            acc.w = fmaf(e, k4.w, acc.w);
        }
    }

    if (lane == 0) { sm_m[w] = m; sm_s[w] = s; }
    sm_acc [w * 32 + lane] = acc;
    sm_ksum[w * 32 + lane] = ksum;
    __syncthreads();

    if (tid < 32) {
        float M = sm_m[0];
        #pragma unroll
        for (int j = 1; j < NW; j++) M = fmaxf(M, sm_m[j]);

        float S = 0.f;
        float4 r = make_float4(0.f, 0.f, 0.f, 0.f);
        float4 k = make_float4(0.f, 0.f, 0.f, 0.f);
        #pragma unroll
        for (int j = 0; j < NW; j++) {
            const float f = __expf(sm_m[j] - M);
            S = fmaf(sm_s[j], f, S);
            const float4 a  = sm_acc [j * 32 + tid];
            const float4 ks = sm_ksum[j * 32 + tid];
            r.x = fmaf(f, a.x, r.x); r.y = fmaf(f, a.y, r.y);
            r.z = fmaf(f, a.z, r.z); r.w = fmaf(f, a.w, r.w);
            k.x += ks.x; k.y += ks.y; k.z += ks.z; k.w += ks.w;
        }
        const float invS = 1.0f / S;
        const float invT = 1.0f / (float)T_;
        float4 o;
        o.x = fmaf(r.x, invS, k.x * invT);
        o.y = fmaf(r.y, invS, k.y * invT);
        o.z = fmaf(r.z, invS, k.z * invT);
        o.w = fmaf(r.w, invS, k.w * invT);
        ((float4*)(out + (size_t)b * C_))[tid] = o;
    }
}

// ---------------------------------------------------------------------------
extern "C" void kernel_launch(void* const* d_in, const int* in_sizes, int n_in,
                              void* d_out, int out_size) {
    const float* uq   = (const float*)d_in[0];   // [B,1,C]
    const float* keys = (const float*)d_in[1];   // [B,T,C]
    const int*   klen = (const int*)d_in[2];     // [B,1]
    const float* W    = (const float*)d_in[3];   // [C,C]
    const float* bias = (const float*)d_in[4];   // [C]
    float* out = (float*)d_out;                  // [B,1,C]

    const int qsmem = (C_ * C_ + QBT * C_) * sizeof(float);   // ~68 KB
    cudaFuncSetAttribute(query_kernel,
                         cudaFuncAttributeMaxDynamicSharedMemorySize, qsmem);

    query_kernel<<<B_ / QBT, THREADS, qsmem>>>(uq, W, bias);
    attn_kernel<<<B_, THREADS>>>(keys, klen, out);
}

// round 3
// speedup vs baseline: 1.6746x; 1.1806x over previous
#include <cuda_runtime.h>
#include <math.h>

#define B_ 2048
#define T_ 200
#define C_ 128
#define THREADS 256
#define NW 8

__global__ void __launch_bounds__(THREADS)
fused_kernel(const float* __restrict__ uq,
             const float* __restrict__ keys,
             const int*   __restrict__ keys_length,
             const float* __restrict__ W,
             const float* __restrict__ bias,
             float*       __restrict__ out) {
    __shared__ float  suq[C_];
    __shared__ float  spart[2][C_];
    __shared__ float  sq[C_];
    __shared__ float  sm_s[NW];
    __shared__ float4 sm_acc[NW * 32];
    __shared__ float4 sm_ksum[NW * 32];

    const int tid  = threadIdx.x;
    const int b    = blockIdx.x;
    const int lane = tid & 31;
    const int w    = tid >> 5;

    // ---- phase 0: q = tanh(uq[b] @ W + bias), W read straight from L2 ----
    if (tid < 32)
        ((float4*)suq)[tid] = ((const float4*)(uq + (size_t)b * C_))[tid];
    __syncthreads();
    {
        const int c = tid & (C_ - 1);
        const int h = tid >> 7;                         // split d-range in half
        const float* Wp = W + (size_t)(h * 64) * C_ + c;
        const float* u  = suq + h * 64;
        float a0 = 0.f, a1 = 0.f, a2 = 0.f, a3 = 0.f;
        #pragma unroll 16
        for (int d = 0; d < 64; d += 4) {
            a0 = fmaf(u[d + 0], Wp[(d + 0) * C_], a0);
            a1 = fmaf(u[d + 1], Wp[(d + 1) * C_], a1);
            a2 = fmaf(u[d + 2], Wp[(d + 2) * C_], a2);
            a3 = fmaf(u[d + 3], Wp[(d + 3) * C_], a3);
        }
        spart[h][c] = (a0 + a1) + (a2 + a3);
    }
    __syncthreads();
    if (tid < C_) sq[tid] = tanhf(spart[0][tid] + spart[1][tid] + bias[tid]);
    __syncthreads();

    // ---- phase 1: single-pass softmax-weighted sum, no max subtraction ----
    const float4  q4  = ((const float4*)sq)[lane];
    const int     len = keys_length[b];
    const float4* gk  = (const float4*)(keys + (size_t)b * T_ * C_);
    const float scale = 0.08838834764831845f;          // 1/sqrt(128)

    float  s0 = 0.f, s1 = 0.f;
    float4 acc0 = make_float4(0.f, 0.f, 0.f, 0.f);
    float4 acc1 = make_float4(0.f, 0.f, 0.f, 0.f);
    float4 ksum = make_float4(0.f, 0.f, 0.f, 0.f);

    #pragma unroll 3
    for (int i = 0; i < 12; i++) {
        const int ta = w + i * 16;
        const int tb = ta + 8;
        const float4 ka = gk[ta * 32 + lane];
        const float4 kb = gk[tb * 32 + lane];

        ksum.x += ka.x + kb.x; ksum.y += ka.y + kb.y;
        ksum.z += ka.z + kb.z; ksum.w += ka.w + kb.w;

        float da = q4.x * ka.x + q4.y * ka.y + q4.z * ka.z + q4.w * ka.w;
        float db = q4.x * kb.x + q4.y * kb.y + q4.z * kb.z + q4.w * kb.w;
        #pragma unroll
        for (int off = 16; off; off >>= 1) {
            da += __shfl_xor_sync(0xffffffffu, da, off);
            db += __shfl_xor_sync(0xffffffffu, db, off);
        }

        const float ea = (ta < len) ? __expf(da * scale) : 0.f;
        const float eb = (tb < len) ? __expf(db * scale) : 0.f;

        s0 += ea; s1 += eb;
        acc0.x = fmaf(ea, ka.x, acc0.x); acc0.y = fmaf(ea, ka.y, acc0.y);
        acc0.z = fmaf(ea, ka.z, acc0.z); acc0.w = fmaf(ea, ka.w, acc0.w);
        acc1.x = fmaf(eb, kb.x, acc1.x); acc1.y = fmaf(eb, kb.y, acc1.y);
        acc1.z = fmaf(eb, kb.z, acc1.z); acc1.w = fmaf(eb, kb.w, acc1.w);
    }
    {   // tail: t = w + 192
        const int t = w + 192;
        const float4 k = gk[t * 32 + lane];
        ksum.x += k.x; ksum.y += k.y; ksum.z += k.z; ksum.w += k.w;
        float d = q4.x * k.x + q4.y * k.y + q4.z * k.z + q4.w * k.w;
        #pragma unroll
        for (int off = 16; off; off >>= 1)
            d += __shfl_xor_sync(0xffffffffu, d, off);
        const float e = (t < len) ? __expf(d * scale) : 0.f;
        s0 += e;
        acc0.x = fmaf(e, k.x, acc0.x); acc0.y = fmaf(e, k.y, acc0.y);
        acc0.z = fmaf(e, k.z, acc0.z); acc0.w = fmaf(e, k.w, acc0.w);
    }

    if (lane == 0) sm_s[w] = s0 + s1;                  // e's are lane-uniform
    acc0.x += acc1.x; acc0.y += acc1.y; acc0.z += acc1.z; acc0.w += acc1.w;
    sm_acc [w * 32 + lane] = acc0;
    sm_ksum[w * 32 + lane] = ksum;
    __syncthreads();

    // ---- epilogue: combine 8 warps, fold residual mean-pool ----
    if (tid < 32) {
        float  S = 0.f;
        float4 r = make_float4(0.f, 0.f, 0.f, 0.f);
        float4 k = make_float4(0.f, 0.f, 0.f, 0.f);
        #pragma unroll
        for (int j = 0; j < NW; j++) {
            S += sm_s[j];
            const float4 a  = sm_acc [j * 32 + tid];
            const float4 ks = sm_ksum[j * 32 + tid];
            r.x += a.x; r.y += a.y; r.z += a.z; r.w += a.w;
            k.x += ks.x; k.y += ks.y; k.z += ks.z; k.w += ks.w;
        }
        const float invT = 1.0f / (float)T_;
        float4 o;
        if (S > 0.f) {
            const float invS = 1.0f / S;
            o.x = fmaf(r.x, invS, k.x * invT);
            o.y = fmaf(r.y, invS, k.y * invT);
            o.z = fmaf(r.z, invS, k.z * invT);
            o.w = fmaf(r.w, invS, k.w * invT);
        } else {                                       // len==0: uniform softmax
            const float u2 = 2.0f * invT;
            o.x = k.x * u2; o.y = k.y * u2; o.z = k.z * u2; o.w = k.w * u2;
        }
        ((float4*)(out + (size_t)b * C_))[tid] = o;
    }
}

// ---------------------------------------------------------------------------
extern "C" void kernel_launch(void* const* d_in, const int* in_sizes, int n_in,
                              void* d_out, int out_size) {
    const float* uq   = (const float*)d_in[0];   // [B,1,C]
    const float* keys = (const float*)d_in[1];   // [B,T,C]
    const int*   klen = (const int*)d_in[2];     // [B,1]
    const float* W    = (const float*)d_in[3];   // [C,C]
    const float* bias = (const float*)d_in[4];   // [C]
    float* out = (float*)d_out;                  // [B,1,C]

    fused_kernel<<<B_, THREADS>>>(uq, keys, klen, W, bias, out);
}